// round 9
// baseline (speedup 1.0000x reference)
#include <cuda_runtime.h>
#include <cstdint>
#include <cstddef>

// ---------------------------------------------------------------------------
// HGNN_conv via tf32 mma.sync:
//   yT  = (x @ W)^T            [128f, 16384n]   (rna-rounded on store)
//   eyT = raw MT @ y, as [f][e], split-K atomics
//   eys = rna(D_v ⊙ ey)
//   out = 0.5 * D_e ⊙ (MT^T @ eys)
// R9: both operands via cp.async in their NATURAL gmem layouts (no LDG->reg
// ->STS staging, no transpose): 2-stage pipeline, wait_group(1), so the next
// stage's DRAM latency rides behind compute. The raw (streamed) operand is
// rna-rounded at the FRAGMENT level: G1/G2 cvt 8 B-words per warp-kstep
// (double-buffered one kstep ahead of the MMAs); G3 cvts its 16 scalar A
// words. Resident operands are pre-rounded, no cvt.
// ---------------------------------------------------------------------------

#define NN   16384
#define NE   8192
#define CIN  256
#define FOUT 128

__device__ float g_yT [FOUT * NN];   // 8 MB
__device__ float g_eyT[FOUT * NE];   // 4 MB
__device__ float g_wt [FOUT * CIN];  // 128 KB

#define BM 128
#define BN 128
#define BK 32
#define NTHR 256
#define SA0 36            // As stride (floats), CONF0 layout [m][k]; 144B
#define SA1 136           // As stride (floats), CONF1 layout [k][m]; 544B
#define SB  36            // Bs stride (floats), [n][k]; 144B
#define STAGE_FLOATS 9216 // 36864 B / 4
#define B_OFF_F 4608      // 18432 B / 4
#define SMEM_BYTES 73728  // 2 stages

// ---------------- helpers ----------------
static __device__ __forceinline__ uint32_t smem_u32(const void* p) {
    uint32_t a;
    asm("{ .reg .u64 t; cvta.to.shared.u64 t, %1; cvt.u32.u64 %0, t; }" : "=r"(a) : "l"(p));
    return a;
}
static __device__ __forceinline__ uint32_t rna(float x) {
    uint32_t o; asm("cvt.rna.tf32.f32 %0, %1;" : "=r"(o) : "f"(x)); return o;
}
static __device__ __forceinline__ float rnaf(float x) { return __uint_as_float(rna(x)); }
static __device__ __forceinline__ uint32_t rna_u(uint32_t x) {
    uint32_t o; asm("cvt.rna.tf32.f32 %0, %1;" : "=r"(o) : "f"(__uint_as_float(x))); return o;
}
static __device__ __forceinline__ void cp16(uint32_t s, const void* g) {
    asm volatile("cp.async.cg.shared.global [%0], [%1], 16;" :: "r"(s), "l"(g) : "memory");
}
static __device__ __forceinline__ void cp_commit() {
    asm volatile("cp.async.commit_group;" ::: "memory");
}
template <int N>
static __device__ __forceinline__ void cp_wait() {
    asm volatile("cp.async.wait_group %0;" :: "n"(N) : "memory");
}
static __device__ __forceinline__ void ldsm4(uint32_t& r0, uint32_t& r1,
                                             uint32_t& r2, uint32_t& r3, uint32_t a) {
    asm volatile("ldmatrix.sync.aligned.m8n8.x4.shared.b16 {%0,%1,%2,%3}, [%4];"
                 : "=r"(r0), "=r"(r1), "=r"(r2), "=r"(r3) : "r"(a));
}
static __device__ __forceinline__ void mma8(float& c0, float& c1, float& c2, float& c3,
                                            uint32_t a0, uint32_t a1, uint32_t a2, uint32_t a3,
                                            uint32_t b0, uint32_t b1) {
    asm volatile("mma.sync.aligned.m16n8k8.row.col.f32.tf32.tf32.f32 "
                 "{%0,%1,%2,%3}, {%4,%5,%6,%7}, {%8,%9}, {%0,%1,%2,%3};"
                 : "+f"(c0), "+f"(c1), "+f"(c2), "+f"(c3)
                 : "r"(a0), "r"(a1), "r"(a2), "r"(a3), "r"(b0), "r"(b1));
}

// ---------------- small kernels ----------------
__global__ void zero2_kernel(float* __restrict__ a, size_t na4,
                             float* __restrict__ b, size_t nb4) {
    size_t i = (size_t)blockIdx.x * blockDim.x + threadIdx.x;
    size_t st = (size_t)gridDim.x * blockDim.x;
    float4 z = make_float4(0.f, 0.f, 0.f, 0.f);
    for (size_t j = i; j < na4; j += st) reinterpret_cast<float4*>(a)[j] = z;
    for (size_t j = i; j < nb4; j += st) reinterpret_cast<float4*>(b)[j] = z;
}
__global__ void prep_wt_kernel(const float* __restrict__ W, float* __restrict__ wt) {
    int idx = blockIdx.x * blockDim.x + threadIdx.x;
    if (idx < FOUT * CIN) {
        int f = idx % FOUT, c = idx / FOUT;
        wt[f * CIN + c] = rnaf(W[c * FOUT + f]);
    }
}
__global__ void scale_ey_kernel(float* __restrict__ eyT, const float* __restrict__ dv) {
    int i4 = blockIdx.x * blockDim.x + threadIdx.x;
    if (i4 < (FOUT * NE) / 4) {
        int e4 = (i4 * 4) & (NE - 1);
        float4 v = reinterpret_cast<float4*>(eyT)[i4];
        const float4 s = *reinterpret_cast<const float4*>(&dv[e4]);
        v.x = rnaf(v.x * s.x); v.y = rnaf(v.y * s.y);
        v.z = rnaf(v.z * s.z); v.w = rnaf(v.w * s.w);
        reinterpret_cast<float4*>(eyT)[i4] = v;
    }
}

// ---------------- main GEMM ----------------
// CONF 0: A resident pre-rounded [m][k] (cp.async, LDSM, no cvt);
//         B streamed RAW [n][k]   (cp.async, LDSM, cvt on fragments)
// CONF 1: A streamed RAW [k][m]   (cp.async — natural MT layout, scalar LDS + cvt);
//         B resident pre-rounded [n][k] (cp.async, LDSM, no cvt)
// EPI  0: direct store with rna   1: atomicAdd   2: atomicAdd * 0.5*rowscale[m]
template <int CONF, int EPI>
__global__ __launch_bounds__(NTHR)
void mmak(const float* __restrict__ Ag, int lda,
          const float* __restrict__ Bg, int ldb,
          float* __restrict__ Cg, int ldc,
          const float* __restrict__ rowscale,
          int k_chunk)
{
    extern __shared__ float sm[];
    const int t    = threadIdx.x;
    const int lane = t & 31, wid = t >> 5;
    const int g = lane >> 2, tg = lane & 3;
    const int wm = (wid & 1) * 64, wn = (wid >> 1) * 32;
    const int m0 = blockIdx.x * BM, n0 = blockIdx.y * BN;
    const int kbase = blockIdx.z * k_chunk;
    const int KT = k_chunk / BK;

    float acc[4][4][4];
    #pragma unroll
    for (int a = 0; a < 4; ++a)
        #pragma unroll
        for (int b = 0; b < 4; ++b)
            #pragma unroll
            for (int c = 0; c < 4; ++c) acc[a][b][c] = 0.f;

    // ldmatrix per-lane offsets (floats) within a stage
    const uint32_t aOffF = (uint32_t)((wm + (lane & 15)) * SA0 + (lane >> 4) * 4);
    const uint32_t bOffF = (uint32_t)((wn + (lane & 7) + (lane >> 4) * 8) * SB
                                      + ((lane >> 3) & 1) * 4);

    // ---- fill stage s (both operands) via cp.async, k-tile kt ----
    auto cp_stage = [&](int s, int kt) {
        const int kk = kbase + kt * BK;
        float* base = sm + s * STAGE_FLOATS;
        if (CONF == 0) {
            const int r = t >> 1, h = t & 1;
            const float* srcA = Ag + (size_t)(m0 + r) * lda + kk + h * 16;
            uint32_t aA = smem_u32(base + r * SA0 + h * 16);
            #pragma unroll
            for (int j = 0; j < 4; ++j) cp16(aA + j * 16, srcA + j * 4);
            const float* srcB = Bg + (size_t)(n0 + r) * ldb + kk + h * 16;
            uint32_t aB = smem_u32(base + B_OFF_F + r * SB + h * 16);
            #pragma unroll
            for (int j = 0; j < 4; ++j) cp16(aB + j * 16, srcB + j * 4);
        } else {
            // A: MT rows are k (m contiguous) — natural [k][m] tile
            const int kr = t >> 3, ml = (t & 7) * 16;
            const float* srcA = Ag + (size_t)(kk + kr) * lda + m0 + ml;
            uint32_t aA = smem_u32(base + kr * SA1 + ml);
            #pragma unroll
            for (int j = 0; j < 4; ++j) cp16(aA + j * 16, srcA + j * 4);
            const int r = t >> 1, h = t & 1;
            const float* srcB = Bg + (size_t)(n0 + r) * ldb + kk + h * 16;
            uint32_t aB = smem_u32(base + B_OFF_F + r * SB + h * 16);
            #pragma unroll
            for (int j = 0; j < 4; ++j) cp16(aB + j * 16, srcB + j * 4);
        }
    };

    // ---- compute one stage ----
    auto compute = [&](int s) {
        const float* As = sm + s * STAGE_FLOATS;
        const float* Bs = As + B_OFF_F;
        const uint32_t aBase = smem_u32(As) + (aOffF << 2);
        const uint32_t bBase = smem_u32(Bs) + (bOffF << 2);

        if (CONF == 0) {
            // B raw: double-buffer fragments one kstep ahead; cvt overlaps MMA
            uint32_t bf[2][4][2];
            auto ldsmB = [&](int ks, uint32_t (*d)[2]) {
                #pragma unroll
                for (int p = 0; p < 2; ++p)
                    ldsm4(d[2*p][0], d[2*p][1], d[2*p+1][0], d[2*p+1][1],
                          bBase + ks * 32 + p * (16 * SB * 4));
            };
            auto cvtB = [&](uint32_t (*d)[2]) {
                #pragma unroll
                for (int ni = 0; ni < 4; ++ni) {
                    d[ni][0] = rna_u(d[ni][0]);
                    d[ni][1] = rna_u(d[ni][1]);
                }
            };
            ldsmB(0, bf[0]);
            cvtB(bf[0]);
            #pragma unroll
            for (int ks = 0; ks < 4; ++ks) {
                const int cur = ks & 1;
                uint32_t af[4][4];
                if (ks < 3) ldsmB(ks + 1, bf[cur ^ 1]);
                #pragma unroll
                for (int mi = 0; mi < 4; ++mi)
                    ldsm4(af[mi][0], af[mi][1], af[mi][2], af[mi][3],
                          aBase + ks * 32 + mi * (16 * SA0 * 4));
                #pragma unroll
                for (int mi = 0; mi < 4; ++mi)
                    #pragma unroll
                    for (int ni = 0; ni < 4; ++ni)
                        mma8(acc[mi][ni][0], acc[mi][ni][1], acc[mi][ni][2], acc[mi][ni][3],
                             af[mi][0], af[mi][1], af[mi][2], af[mi][3],
                             bf[cur][ni][0], bf[cur][ni][1]);
                if (ks < 3) cvtB(bf[cur ^ 1]);
            }
        } else {
            // A raw scalar [k][m] + cvt; B pre-rounded LDSM
            #pragma unroll
            for (int ks = 0; ks < 4; ++ks) {
                const int k8 = ks * 8;
                uint32_t af[4][4], bf[4][2];
                #pragma unroll
                for (int mi = 0; mi < 4; ++mi) {
                    const int r0 = wm + mi * 16 + g, r1 = r0 + 8;
                    const int c0 = k8 + tg, c1 = c0 + 4;
                    af[mi][0] = __float_as_uint(As[c0 * SA1 + r0]);
                    af[mi][1] = __float_as_uint(As[c0 * SA1 + r1]);
                    af[mi][2] = __float_as_uint(As[c1 * SA1 + r0]);
                    af[mi][3] = __float_as_uint(As[c1 * SA1 + r1]);
                }
                #pragma unroll
                for (int mi = 0; mi < 4; ++mi) {
                    af[mi][0] = rna_u(af[mi][0]); af[mi][1] = rna_u(af[mi][1]);
                    af[mi][2] = rna_u(af[mi][2]); af[mi][3] = rna_u(af[mi][3]);
                }
                #pragma unroll
                for (int p = 0; p < 2; ++p)
                    ldsm4(bf[2*p][0], bf[2*p][1], bf[2*p+1][0], bf[2*p+1][1],
                          bBase + ks * 32 + p * (16 * SB * 4));
                #pragma unroll
                for (int mi = 0; mi < 4; ++mi)
                    #pragma unroll
                    for (int ni = 0; ni < 4; ++ni)
                        mma8(acc[mi][ni][0], acc[mi][ni][1], acc[mi][ni][2], acc[mi][ni][3],
                             af[mi][0], af[mi][1], af[mi][2], af[mi][3],
                             bf[ni][0], bf[ni][1]);
            }
        }
    };

    // ---- 2-stage cp.async pipeline ----
    cp_stage(0, 0);
    cp_commit();
    for (int kt = 0; kt < KT; ++kt) {
        const int cur = kt & 1, nxt = cur ^ 1;
        const bool more = (kt + 1 < KT);
        if (more) {
            cp_stage(nxt, kt + 1);   // in flight across compute(cur)
            cp_commit();
            cp_wait<1>();            // cur's group complete
        } else {
            cp_wait<0>();
        }
        __syncthreads();
        compute(cur);
        __syncthreads();
    }

    // ---- epilogue ----
    #pragma unroll
    for (int mi = 0; mi < 4; ++mi) {
        const int r0 = m0 + wm + mi * 16 + g;
        const int r1 = r0 + 8;
        #pragma unroll
        for (int ni = 0; ni < 4; ++ni) {
            const int c0 = n0 + wn + ni * 8 + tg * 2;
            float* p0 = Cg + (size_t)r0 * ldc + c0;
            float* p1 = Cg + (size_t)r1 * ldc + c0;
            if (EPI == 0) {
                p0[0] = rnaf(acc[mi][ni][0]); p0[1] = rnaf(acc[mi][ni][1]);
                p1[0] = rnaf(acc[mi][ni][2]); p1[1] = rnaf(acc[mi][ni][3]);
            } else if (EPI == 1) {
                atomicAdd(&p0[0], acc[mi][ni][0]); atomicAdd(&p0[1], acc[mi][ni][1]);
                atomicAdd(&p1[0], acc[mi][ni][2]); atomicAdd(&p1[1], acc[mi][ni][3]);
            } else {
                const float s0 = 0.5f * rowscale[r0];
                const float s1 = 0.5f * rowscale[r1];
                atomicAdd(&p0[0], s0 * acc[mi][ni][0]); atomicAdd(&p0[1], s0 * acc[mi][ni][1]);
                atomicAdd(&p1[0], s1 * acc[mi][ni][2]); atomicAdd(&p1[1], s1 * acc[mi][ni][3]);
            }
        }
    }
}

// ---------------- launch ----------------
extern "C" void kernel_launch(void* const* d_in, const int* in_sizes, int n_in,
                              void* d_out, int out_size) {
    const float *x = nullptr, *w = nullptr, *mt = nullptr, *dv = nullptr, *de = nullptr;
    for (int i = 0; i < n_in; ++i) {
        switch (in_sizes[i]) {
            case NN * CIN:   x  = (const float*)d_in[i]; break;
            case CIN * FOUT: w  = (const float*)d_in[i]; break;
            case 134217728:  mt = (const float*)d_in[i]; break;
            case NE:         dv = (const float*)d_in[i]; break;
            case NN:         de = (const float*)d_in[i]; break;
        }
    }
    float* out = (float*)d_out;
    float *yT, *eyT, *wt;
    { void* p; cudaGetSymbolAddress(&p, g_yT);  yT  = (float*)p; }
    { void* p; cudaGetSymbolAddress(&p, g_eyT); eyT = (float*)p; }
    { void* p; cudaGetSymbolAddress(&p, g_wt);  wt  = (float*)p; }

    cudaFuncSetAttribute(mmak<0, 0>, cudaFuncAttributeMaxDynamicSharedMemorySize, SMEM_BYTES);
    cudaFuncSetAttribute(mmak<0, 1>, cudaFuncAttributeMaxDynamicSharedMemorySize, SMEM_BYTES);
    cudaFuncSetAttribute(mmak<1, 2>, cudaFuncAttributeMaxDynamicSharedMemorySize, SMEM_BYTES);

    zero2_kernel<<<512, 256>>>(eyT, (size_t)(FOUT * NE) / 4, out, (size_t)(NN * FOUT) / 4);
    prep_wt_kernel<<<(FOUT * CIN + 255) / 256, 256>>>(w, wt);

    // G1: yT[f][n] = rna( sum_c wt[f][c] * x[n][c] )
    mmak<0, 0><<<dim3(1, NN / BN, 1), NTHR, SMEM_BYTES>>>(
        wt, CIN, x, CIN, yT, NN, nullptr, CIN);

    // G2: eyT[f][e] += sum_n yT[f][n] * MT[e][n]   (split-K = 4)
    mmak<0, 1><<<dim3(1, NE / BN, 4), NTHR, SMEM_BYTES>>>(
        yT, NN, mt, NN, eyT, NE, nullptr, NN / 4);

    scale_ey_kernel<<<(FOUT * NE / 4 + 255) / 256, 256>>>(eyT, dv);

    // G3: out[v][f] += 0.5*De[v] * sum_e MT[e][v] * eyT[f][e]   (split-K = 2)
    mmak<1, 2><<<dim3(NN / BM, 1, 2), NTHR, SMEM_BYTES>>>(
        mt, NN, eyT, NE, out, FOUT, de, NE / 2);
}